// round 1
// baseline (speedup 1.0000x reference)
#include <cuda_runtime.h>
#include <math.h>
#include <stdint.h>

// ---------------------------------------------------------------------------
// PointNet++ encoder forward.
// B = 32*64 = 2048 point clouds, N = 1024 points, 6 channels (xyz + 3 feats).
// SA1: fps 32 centers, ball r=0.2 ns=32, MLP 6->64->64->128, max  -> [B,32,128]
// SA2: fps 16 centers, ball r=0.4 ns=32, MLP 131->128->128->256, max -> [B,16,256]
// Head: concat(xyz,feat)=259 -> 256 -> 512 -> 768, max over 16, FC 768->768
// ---------------------------------------------------------------------------

#define B_TOT 2048
#define N1    1024
#define M1    32
#define M2    16
#define NSMP  32

// Scratch (device globals; no runtime allocation allowed)
__device__ int   g_fps1 [B_TOT * M1];
__device__ float g_nx1  [B_TOT * M1 * 3];
__device__ int   g_ball1[B_TOT * M1 * NSMP];
__device__ float g_f1   [B_TOT * M1 * 128];
__device__ int   g_fps2 [B_TOT * M2];
__device__ float g_nx2  [B_TOT * M2 * 3];
__device__ int   g_ball2[B_TOT * M2 * NSMP];
__device__ float g_f2   [B_TOT * M2 * 256];

// ---------------------------------------------------------------------------
// FPS stage 1: block per batch, 1024 threads (one per point).
// Matches reference: first pick = 0; dist = min(dist, |x - last|^2); argmax.
// Distance computed un-fused, left-to-right, like the reference elementwise op.
// ---------------------------------------------------------------------------
__global__ void fps1_kernel(const float* __restrict__ x,
                            int* __restrict__ fidx, float* __restrict__ nxyz) {
    __shared__ float sv[1024];
    __shared__ int   si[1024];
    __shared__ float cur[3];
    const int b = blockIdx.x;
    const int t = threadIdx.x;
    const float* p = x + ((size_t)b * N1 + t) * 6;
    const float px = p[0], py = p[1], pz = p[2];
    float dist = 1e10f;
    if (t == 0) {
        fidx[b * M1] = 0;
        float* o = nxyz + (size_t)b * M1 * 3;
        o[0] = px; o[1] = py; o[2] = pz;
    }
    int last = 0;
    for (int it = 1; it < M1; ++it) {
        if (t == last) { cur[0] = px; cur[1] = py; cur[2] = pz; }
        __syncthreads();
        float dx = __fsub_rn(px, cur[0]);
        float dy = __fsub_rn(py, cur[1]);
        float dz = __fsub_rn(pz, cur[2]);
        float d  = __fadd_rn(__fadd_rn(__fmul_rn(dx, dx), __fmul_rn(dy, dy)),
                             __fmul_rn(dz, dz));
        dist = fminf(dist, d);
        sv[t] = dist; si[t] = t;
        __syncthreads();
        // argmax, tie -> smaller index (jnp.argmax first-occurrence)
        for (int s = 512; s >= 1; s >>= 1) {
            if (t < s) {
                float ov = sv[t + s]; int oi = si[t + s];
                if (ov > sv[t] || (ov == sv[t] && oi < si[t])) {
                    sv[t] = ov; si[t] = oi;
                }
            }
            __syncthreads();
        }
        last = si[0];
        if (t == 0) fidx[b * M1 + it] = last;
        if (t == last) {
            float* o = nxyz + ((size_t)b * M1 + it) * 3;
            o[0] = px; o[1] = py; o[2] = pz;
        }
        __syncthreads();
    }
}

// ---------------------------------------------------------------------------
// FPS stage 2: warp per batch, 32 points -> 16 centers. Shuffle argmax.
// ---------------------------------------------------------------------------
__global__ void fps2_kernel(const float* __restrict__ pts,
                            int* __restrict__ fidx, float* __restrict__ nxyz) {
    const int gw   = (blockIdx.x * blockDim.x + threadIdx.x) >> 5;
    const int lane = threadIdx.x & 31;
    if (gw >= B_TOT) return;
    const float* pb = pts + (size_t)gw * M1 * 3;
    const float px = pb[lane * 3 + 0], py = pb[lane * 3 + 1], pz = pb[lane * 3 + 2];
    float dist = 1e10f;
    if (lane == 0) {
        fidx[gw * M2] = 0;
        float* o = nxyz + (size_t)gw * M2 * 3;
        o[0] = px; o[1] = py; o[2] = pz;
    }
    int last = 0;
    for (int it = 1; it < M2; ++it) {
        const float cx = __shfl_sync(0xffffffffu, px, last);
        const float cy = __shfl_sync(0xffffffffu, py, last);
        const float cz = __shfl_sync(0xffffffffu, pz, last);
        float dx = __fsub_rn(px, cx), dy = __fsub_rn(py, cy), dz = __fsub_rn(pz, cz);
        float d  = __fadd_rn(__fadd_rn(__fmul_rn(dx, dx), __fmul_rn(dy, dy)),
                             __fmul_rn(dz, dz));
        dist = fminf(dist, d);
        float v = dist; int vi = lane;
        #pragma unroll
        for (int off = 16; off; off >>= 1) {
            float v2 = __shfl_xor_sync(0xffffffffu, v, off);
            int   i2 = __shfl_xor_sync(0xffffffffu, vi, off);
            if (v2 > v || (v2 == v && i2 < vi)) { v = v2; vi = i2; }
        }
        last = vi;
        if (lane == 0) fidx[gw * M2 + it] = last;
        if (lane == last) {
            float* o = nxyz + ((size_t)gw * M2 + it) * 3;
            o[0] = px; o[1] = py; o[2] = pz;
        }
    }
}

// ---------------------------------------------------------------------------
// Ball query: warp per (batch, center). Expanded distance form, exactly like
// the reference: (|c|^2 + |p|^2) - 2*(c.p), all rn / un-fused.
// First NSMP indices in increasing order with d2 < r2, padded with first hit.
// ---------------------------------------------------------------------------
__global__ void ball_kernel(const float* __restrict__ pts, int pstride,
                            const float* __restrict__ centers,
                            int M, int N, float r2, int* __restrict__ out) {
    const int gw   = (blockIdx.x * blockDim.x + threadIdx.x) >> 5;
    const int lane = threadIdx.x & 31;
    if (gw >= B_TOT * M) return;
    const int b = gw / M;
    const float* c = centers + (size_t)gw * 3;
    const float cx = c[0], cy = c[1], cz = c[2];
    const float cn = __fadd_rn(__fadd_rn(__fmul_rn(cx, cx), __fmul_rn(cy, cy)),
                               __fmul_rn(cz, cz));
    int* o = out + (size_t)gw * NSMP;
    int cnt = 0, first = -1;
    for (int base = 0; base < N && cnt < NSMP; base += 32) {
        const float* pp = pts + ((size_t)b * N + base + lane) * pstride;
        const float px = pp[0], py = pp[1], pz = pp[2];
        const float pn = __fadd_rn(__fadd_rn(__fmul_rn(px, px), __fmul_rn(py, py)),
                                   __fmul_rn(pz, pz));
        const float dt = __fadd_rn(__fadd_rn(__fmul_rn(cx, px), __fmul_rn(cy, py)),
                                   __fmul_rn(cz, pz));
        const float d2 = __fsub_rn(__fadd_rn(cn, pn), __fmul_rn(2.0f, dt));
        const bool hit = d2 < r2;
        const unsigned mask = __ballot_sync(0xffffffffu, hit);
        if (first < 0 && mask) first = base + __ffs(mask) - 1;
        const int pos = cnt + __popc(mask & ((1u << lane) - 1u));
        if (hit && pos < NSMP) o[pos] = base + lane;
        cnt += __popc(mask);
    }
    if (cnt > NSMP) cnt = NSMP;
    for (int k = cnt + lane; k < NSMP; k += 32) o[k] = first;
}

// ---------------------------------------------------------------------------
// MLP layer: hout[s][o] = relu((sum_k hin[s][k]*w[k][o] + b[o]) * BN_SCALE).
// Each thread owns 4 consecutive output channels (float4 weight loads).
// ---------------------------------------------------------------------------
template <int NS, int Cin, int Cout, int NT>
__device__ __forceinline__ void mlp_layer(const float* __restrict__ hin,
                                          float* __restrict__ hout,
                                          const float* __restrict__ w,
                                          const float* __restrict__ bias) {
    const float BNS = (float)(1.0 / sqrt(1.0 + 1e-5));
    constexpr int G = Cout / 4;
    for (int task = threadIdx.x; task < NS * G; task += NT) {
        const int s = task / G, g = task % G;
        const float* hr = hin + s * Cin;
        const float4 bv = *reinterpret_cast<const float4*>(bias + 4 * g);
        float ax = bv.x, ay = bv.y, az = bv.z, aw = bv.w;
        const float* wp = w + 4 * g;
        #pragma unroll 4
        for (int k = 0; k < Cin; ++k) {
            const float hv = hr[k];
            const float4 wv = *reinterpret_cast<const float4*>(wp + (size_t)k * Cout);
            ax = fmaf(hv, wv.x, ax); ay = fmaf(hv, wv.y, ay);
            az = fmaf(hv, wv.z, az); aw = fmaf(hv, wv.w, aw);
        }
        float4 r;
        r.x = fmaxf(ax * BNS, 0.0f); r.y = fmaxf(ay * BNS, 0.0f);
        r.z = fmaxf(az * BNS, 0.0f); r.w = fmaxf(aw * BNS, 0.0f);
        *reinterpret_cast<float4*>(hout + s * Cout + 4 * g) = r;
    }
}

// ---------------------------------------------------------------------------
// SA grouped MLP + maxpool: block per (batch, center).
// Input row s: [xyz(point)-center (3), feats (CF)], then 3 MLP layers, max over NS.
// ---------------------------------------------------------------------------
template <int NS, int CF, int C1, int C2, int C3, int NT>
__global__ void sa_mlp_kernel(const float* __restrict__ pts, int pstride,
                              const float* __restrict__ feats, int fstride,
                              const float* __restrict__ centers,
                              const int* __restrict__ ball,
                              const float* __restrict__ w0, const float* __restrict__ b0,
                              const float* __restrict__ w1, const float* __restrict__ b1,
                              const float* __restrict__ w2, const float* __restrict__ b2,
                              float* __restrict__ out, int M, int N) {
    constexpr int C0 = 3 + CF;
    constexpr int AE = NS * (C0 > C2 ? C0 : C2);
    extern __shared__ float smem[];
    float* bufA = smem;
    float* bufB = smem + AE;
    const int bm = blockIdx.x;
    const int b  = bm / M;
    const int* bi = ball + (size_t)bm * NS;
    const float* ctr = centers + (size_t)bm * 3;

    for (int i = threadIdx.x; i < NS * C0; i += NT) {
        const int s = i / C0, c = i % C0;
        const int p = bi[s];
        float v;
        if (c < 3) v = pts[((size_t)b * N + p) * pstride + c] - ctr[c];
        else       v = feats[((size_t)b * N + p) * fstride + (c - 3)];
        bufA[s * C0 + c] = v;
    }
    __syncthreads();
    mlp_layer<NS, C0, C1, NT>(bufA, bufB, w0, b0); __syncthreads();
    mlp_layer<NS, C1, C2, NT>(bufB, bufA, w1, b1); __syncthreads();
    mlp_layer<NS, C2, C3, NT>(bufA, bufB, w2, b2); __syncthreads();
    float* o = out + (size_t)bm * C3;
    for (int c = threadIdx.x; c < C3; c += NT) {
        float m = bufB[c];
        #pragma unroll 4
        for (int s = 1; s < NS; ++s) m = fmaxf(m, bufB[s * C3 + c]);
        o[c] = m;
    }
}

// ---------------------------------------------------------------------------
// Head: block per batch. concat(xyz2, feats2) [16,259] -> 256 -> 512 -> 768,
// max over 16 -> g[768], then out = g @ fc_w + fc_b.
// ---------------------------------------------------------------------------
__global__ void final_kernel(const float* __restrict__ nx2, const float* __restrict__ f2,
                             const float* __restrict__ w0, const float* __restrict__ b0,
                             const float* __restrict__ w1, const float* __restrict__ b1,
                             const float* __restrict__ w2, const float* __restrict__ b2,
                             const float* __restrict__ fcw, const float* __restrict__ fcb,
                             float* __restrict__ out) {
    constexpr int NS = 16, C0 = 259, C1 = 256, C2 = 512, C3 = 768, NT = 256;
    constexpr int AE = NS * C2;  // max(C0, C2) = 512
    extern __shared__ float smem[];
    float* bufA = smem;
    float* bufB = smem + AE;
    const int b = blockIdx.x;

    for (int i = threadIdx.x; i < NS * C0; i += NT) {
        const int s = i / C0, c = i % C0;
        float v = (c < 3) ? nx2[((size_t)b * NS + s) * 3 + c]
                          : f2[((size_t)b * NS + s) * 256 + (c - 3)];
        bufA[s * C0 + c] = v;
    }
    __syncthreads();
    mlp_layer<NS, C0, C1, NT>(bufA, bufB, w0, b0); __syncthreads();
    mlp_layer<NS, C1, C2, NT>(bufB, bufA, w1, b1); __syncthreads();
    mlp_layer<NS, C2, C3, NT>(bufA, bufB, w2, b2); __syncthreads();
    float* g = bufA;  // h2 (bufA) is dead after layer 3
    for (int c = threadIdx.x; c < C3; c += NT) {
        float m = bufB[c];
        #pragma unroll 4
        for (int s = 1; s < NS; ++s) m = fmaxf(m, bufB[s * C3 + c]);
        g[c] = m;
    }
    __syncthreads();
    float* o = out + (size_t)b * 768;
    for (int gi = threadIdx.x; gi < 768 / 4; gi += NT) {
        float4 acc = *reinterpret_cast<const float4*>(fcb + 4 * gi);
        #pragma unroll 4
        for (int k = 0; k < 768; ++k) {
            const float gv = g[k];
            const float4 wv = *reinterpret_cast<const float4*>(fcw + (size_t)k * 768 + 4 * gi);
            acc.x = fmaf(gv, wv.x, acc.x); acc.y = fmaf(gv, wv.y, acc.y);
            acc.z = fmaf(gv, wv.z, acc.z); acc.w = fmaf(gv, wv.w, acc.w);
        }
        *reinterpret_cast<float4*>(o + 4 * gi) = acc;
    }
}

// ---------------------------------------------------------------------------
// Host launcher
// ---------------------------------------------------------------------------
extern "C" void kernel_launch(void* const* d_in, const int* in_sizes, int n_in,
                              void* d_out, int out_size) {
    const float* x   = (const float*)d_in[0];
    const float* w10 = (const float*)d_in[1];  const float* b10 = (const float*)d_in[2];
    const float* w11 = (const float*)d_in[3];  const float* b11 = (const float*)d_in[4];
    const float* w12 = (const float*)d_in[5];  const float* b12 = (const float*)d_in[6];
    const float* w20 = (const float*)d_in[7];  const float* b20 = (const float*)d_in[8];
    const float* w21 = (const float*)d_in[9];  const float* b21 = (const float*)d_in[10];
    const float* w22 = (const float*)d_in[11]; const float* b22 = (const float*)d_in[12];
    const float* w30 = (const float*)d_in[13]; const float* b30 = (const float*)d_in[14];
    const float* w31 = (const float*)d_in[15]; const float* b31 = (const float*)d_in[16];
    const float* w32 = (const float*)d_in[17]; const float* b32 = (const float*)d_in[18];
    const float* fcw = (const float*)d_in[19]; const float* fcb = (const float*)d_in[20];
    float* out = (float*)d_out;

    int *fps1p, *ball1p, *fps2p, *ball2p;
    float *nx1p, *f1p, *nx2p, *f2p;
    cudaGetSymbolAddress((void**)&fps1p,  g_fps1);
    cudaGetSymbolAddress((void**)&nx1p,   g_nx1);
    cudaGetSymbolAddress((void**)&ball1p, g_ball1);
    cudaGetSymbolAddress((void**)&f1p,    g_f1);
    cudaGetSymbolAddress((void**)&fps2p,  g_fps2);
    cudaGetSymbolAddress((void**)&nx2p,   g_nx2);
    cudaGetSymbolAddress((void**)&ball2p, g_ball2);
    cudaGetSymbolAddress((void**)&f2p,    g_f2);

    auto sa1 = sa_mlp_kernel<32, 3, 64, 64, 128, 128>;
    auto sa2 = sa_mlp_kernel<32, 128, 128, 128, 256, 256>;

    const int SA1_SMEM   = (32 * 64 + 32 * 128) * 4;      // 24576
    const int SA2_SMEM   = (32 * 131 + 32 * 256) * 4;     // 49536 (>48KB)
    const int FINAL_SMEM = (16 * 512 + 16 * 768) * 4;     // 81920

    cudaFuncSetAttribute(sa2, cudaFuncAttributeMaxDynamicSharedMemorySize, SA2_SMEM);
    cudaFuncSetAttribute(final_kernel, cudaFuncAttributeMaxDynamicSharedMemorySize, FINAL_SMEM);

    // SA1
    fps1_kernel<<<B_TOT, 1024>>>(x, fps1p, nx1p);
    ball_kernel<<<(B_TOT * M1 * 32 + 255) / 256, 256>>>(
        x, 6, nx1p, M1, N1, (float)(0.2 * 0.2), ball1p);
    sa1<<<B_TOT * M1, 128, SA1_SMEM>>>(x, 6, x + 3, 6, nx1p, ball1p,
                                       w10, b10, w11, b11, w12, b12, f1p, M1, N1);
    // SA2
    fps2_kernel<<<(B_TOT * 32 + 127) / 128, 128>>>(nx1p, fps2p, nx2p);
    ball_kernel<<<(B_TOT * M2 * 32 + 255) / 256, 256>>>(
        nx1p, 3, nx2p, M2, M1, (float)(0.4 * 0.4), ball2p);
    sa2<<<B_TOT * M2, 256, SA2_SMEM>>>(nx1p, 3, f1p, 128, nx2p, ball2p,
                                       w20, b20, w21, b21, w22, b22, f2p, M2, M1);
    // Head
    final_kernel<<<B_TOT, 256, FINAL_SMEM>>>(nx2p, f2p, w30, b30, w31, b31,
                                             w32, b32, fcw, fcb, out);
}

// round 2
// speedup vs baseline: 2.3646x; 2.3646x over previous
#include <cuda_runtime.h>
#include <math.h>
#include <stdint.h>

// ---------------------------------------------------------------------------
// PointNet++ encoder forward. B=2048 clouds, N=1024 pts, 6 ch.
// SA1: fps 32, ball r=.2 ns=32, MLP 6->64->64->128, max
// SA2: fps 16, ball r=.4 ns=32, MLP 131->128->128->256, max
// Head: 259 -> 256 -> 512 -> 768, max over 16, FC 768->768
// ---------------------------------------------------------------------------

#define B_TOT 2048
#define N1    1024
#define M1    32
#define M2    16
#define NSMP  32

__device__ int   g_fps1 [B_TOT * M1];
__device__ float g_nx1  [B_TOT * M1 * 3];
__device__ int   g_ball1[B_TOT * M1 * NSMP];
__device__ float g_f1   [B_TOT * M1 * 128];
__device__ int   g_fps2 [B_TOT * M2];
__device__ float g_nx2  [B_TOT * M2 * 3];
__device__ int   g_ball2[B_TOT * M2 * NSMP];
__device__ float g_f2   [B_TOT * M2 * 256];
__device__ float g_g    [B_TOT * 768];

// ---- packed f32x2 helpers (sm_103a FFMA2 path) ------------------------------
typedef unsigned long long ull_t;

__device__ __forceinline__ ull_t pk2(float lo, float hi) {
    ull_t r;
    asm("mov.b64 %0, {%1, %2};" : "=l"(r)
        : "r"(__float_as_uint(lo)), "r"(__float_as_uint(hi)));
    return r;
}
__device__ __forceinline__ ull_t dup2(float v) {
    ull_t r; unsigned u = __float_as_uint(v);
    asm("mov.b64 %0, {%1, %1};" : "=l"(r) : "r"(u));
    return r;
}
__device__ __forceinline__ float2 unpk(ull_t p) {
    unsigned lo, hi;
    asm("mov.b64 {%0, %1}, %2;" : "=r"(lo), "=r"(hi) : "l"(p));
    return make_float2(__uint_as_float(lo), __uint_as_float(hi));
}
#define FMA2(d, a, b, c) \
    asm("fma.rn.f32x2 %0, %1, %2, %3;" : "=l"(d) : "l"(a), "l"(b), "l"(c))

// ---------------------------------------------------------------------------
// FPS stage 1: block per batch, 1024 threads. Warp-shuffle argmax + one
// cross-warp reduce (3 syncs/iter). Math identical to the reference.
// ---------------------------------------------------------------------------
__global__ void fps1_kernel(const float* __restrict__ x,
                            int* __restrict__ fidx, float* __restrict__ nxyz) {
    __shared__ float swv[32];
    __shared__ int   swi[32];
    __shared__ float cur[3];
    __shared__ int   slast;
    const int b = blockIdx.x;
    const int t = threadIdx.x;
    const int warp = t >> 5, lane = t & 31;
    const float* p = x + ((size_t)b * N1 + t) * 6;
    const float px = p[0], py = p[1], pz = p[2];
    float dist = 1e10f;
    if (t == 0) {
        fidx[b * M1] = 0;
        float* o = nxyz + (size_t)b * M1 * 3;
        o[0] = px; o[1] = py; o[2] = pz;
    }
    int last = 0;
    for (int it = 1; it < M1; ++it) {
        if (t == last) { cur[0] = px; cur[1] = py; cur[2] = pz; }
        __syncthreads();
        float dx = __fsub_rn(px, cur[0]);
        float dy = __fsub_rn(py, cur[1]);
        float dz = __fsub_rn(pz, cur[2]);
        float d  = __fadd_rn(__fadd_rn(__fmul_rn(dx, dx), __fmul_rn(dy, dy)),
                             __fmul_rn(dz, dz));
        dist = fminf(dist, d);
        // warp argmax (tie -> smaller index)
        float v = dist; int vi = t;
        #pragma unroll
        for (int off = 16; off; off >>= 1) {
            float v2 = __shfl_xor_sync(0xffffffffu, v, off);
            int   i2 = __shfl_xor_sync(0xffffffffu, vi, off);
            if (v2 > v || (v2 == v && i2 < vi)) { v = v2; vi = i2; }
        }
        if (lane == 0) { swv[warp] = v; swi[warp] = vi; }
        __syncthreads();
        if (warp == 0) {
            float wv = swv[lane]; int wi = swi[lane];
            #pragma unroll
            for (int off = 16; off; off >>= 1) {
                float v2 = __shfl_xor_sync(0xffffffffu, wv, off);
                int   i2 = __shfl_xor_sync(0xffffffffu, wi, off);
                if (v2 > wv || (v2 == wv && i2 < wi)) { wv = v2; wi = i2; }
            }
            if (lane == 0) { slast = wi; fidx[b * M1 + it] = wi; }
        }
        __syncthreads();
        last = slast;
        if (t == last) {
            float* o = nxyz + ((size_t)b * M1 + it) * 3;
            o[0] = px; o[1] = py; o[2] = pz;
        }
    }
}

// ---------------------------------------------------------------------------
// FPS stage 2: warp per batch, 32 points -> 16 centers.
// ---------------------------------------------------------------------------
__global__ void fps2_kernel(const float* __restrict__ pts,
                            int* __restrict__ fidx, float* __restrict__ nxyz) {
    const int gw   = (blockIdx.x * blockDim.x + threadIdx.x) >> 5;
    const int lane = threadIdx.x & 31;
    if (gw >= B_TOT) return;
    const float* pb = pts + (size_t)gw * M1 * 3;
    const float px = pb[lane * 3 + 0], py = pb[lane * 3 + 1], pz = pb[lane * 3 + 2];
    float dist = 1e10f;
    if (lane == 0) {
        fidx[gw * M2] = 0;
        float* o = nxyz + (size_t)gw * M2 * 3;
        o[0] = px; o[1] = py; o[2] = pz;
    }
    int last = 0;
    for (int it = 1; it < M2; ++it) {
        const float cx = __shfl_sync(0xffffffffu, px, last);
        const float cy = __shfl_sync(0xffffffffu, py, last);
        const float cz = __shfl_sync(0xffffffffu, pz, last);
        float dx = __fsub_rn(px, cx), dy = __fsub_rn(py, cy), dz = __fsub_rn(pz, cz);
        float d  = __fadd_rn(__fadd_rn(__fmul_rn(dx, dx), __fmul_rn(dy, dy)),
                             __fmul_rn(dz, dz));
        dist = fminf(dist, d);
        float v = dist; int vi = lane;
        #pragma unroll
        for (int off = 16; off; off >>= 1) {
            float v2 = __shfl_xor_sync(0xffffffffu, v, off);
            int   i2 = __shfl_xor_sync(0xffffffffu, vi, off);
            if (v2 > v || (v2 == v && i2 < vi)) { v = v2; vi = i2; }
        }
        last = vi;
        if (lane == 0) fidx[gw * M2 + it] = last;
        if (lane == last) {
            float* o = nxyz + ((size_t)gw * M2 + it) * 3;
            o[0] = px; o[1] = py; o[2] = pz;
        }
    }
}

// ---------------------------------------------------------------------------
// Ball query (expanded distance form, identical to reference einsum path).
// ---------------------------------------------------------------------------
__global__ void ball_kernel(const float* __restrict__ pts, int pstride,
                            const float* __restrict__ centers,
                            int M, int N, float r2, int* __restrict__ out) {
    const int gw   = (blockIdx.x * blockDim.x + threadIdx.x) >> 5;
    const int lane = threadIdx.x & 31;
    if (gw >= B_TOT * M) return;
    const int b = gw / M;
    const float* c = centers + (size_t)gw * 3;
    const float cx = c[0], cy = c[1], cz = c[2];
    const float cn = __fadd_rn(__fadd_rn(__fmul_rn(cx, cx), __fmul_rn(cy, cy)),
                               __fmul_rn(cz, cz));
    int* o = out + (size_t)gw * NSMP;
    int cnt = 0, first = -1;
    for (int base = 0; base < N && cnt < NSMP; base += 32) {
        const float* pp = pts + ((size_t)b * N + base + lane) * pstride;
        const float px = pp[0], py = pp[1], pz = pp[2];
        const float pn = __fadd_rn(__fadd_rn(__fmul_rn(px, px), __fmul_rn(py, py)),
                                   __fmul_rn(pz, pz));
        const float dt = __fadd_rn(__fadd_rn(__fmul_rn(cx, px), __fmul_rn(cy, py)),
                                   __fmul_rn(cz, pz));
        const float d2 = __fsub_rn(__fadd_rn(cn, pn), __fmul_rn(2.0f, dt));
        const bool hit = d2 < r2;
        const unsigned mask = __ballot_sync(0xffffffffu, hit);
        if (first < 0 && mask) first = base + __ffs(mask) - 1;
        const int pos = cnt + __popc(mask & ((1u << lane) - 1u));
        if (hit && pos < NSMP) o[pos] = base + lane;
        cnt += __popc(mask);
    }
    if (cnt > NSMP) cnt = NSMP;
    for (int k = cnt + lane; k < NSMP; k += 32) o[k] = first;
}

// ---------------------------------------------------------------------------
// MLP layer: sample-blocked (SB samples/thread) + packed f32x2 accumulators.
// Per k: 1 LDG.128 (weights, paired for free) + SB broadcast LDS + SB dup movs
// + 2*SB FFMA2.  FMA-pipe bound.
// ---------------------------------------------------------------------------
template <int NS, int Cin, int Cout, int NT, int SB>
__device__ __forceinline__ void mlp_layer(const float* __restrict__ hin,
                                          float* __restrict__ hout,
                                          const float* __restrict__ w,
                                          const float* __restrict__ bias) {
    const float BNS = (float)(1.0 / sqrt(1.0 + 1e-5));
    constexpr int OG = Cout / 4;
    constexpr int SG = NS / SB;
    for (int task = threadIdx.x; task < OG * SG; task += NT) {
        const int og = task % OG;
        const int sg = task / OG;
        const float4 bv = *reinterpret_cast<const float4*>(bias + 4 * og);
        const ull_t b01 = pk2(bv.x, bv.y), b23 = pk2(bv.z, bv.w);
        ull_t a01[SB], a23[SB];
        #pragma unroll
        for (int i = 0; i < SB; ++i) { a01[i] = b01; a23[i] = b23; }
        const float* wp = w + 4 * og;
        const float* hp = hin + sg * SB * Cin;
        #pragma unroll 2
        for (int k = 0; k < Cin; ++k) {
            const ulonglong2 wq =
                *reinterpret_cast<const ulonglong2*>(wp + (size_t)k * Cout);
            #pragma unroll
            for (int i = 0; i < SB; ++i) {
                const ull_t hh = dup2(hp[i * Cin + k]);
                FMA2(a01[i], hh, wq.x, a01[i]);
                FMA2(a23[i], hh, wq.y, a23[i]);
            }
        }
        #pragma unroll
        for (int i = 0; i < SB; ++i) {
            const float2 p0 = unpk(a01[i]);
            const float2 p1 = unpk(a23[i]);
            float4 r;
            r.x = fmaxf(p0.x * BNS, 0.0f); r.y = fmaxf(p0.y * BNS, 0.0f);
            r.z = fmaxf(p1.x * BNS, 0.0f); r.w = fmaxf(p1.y * BNS, 0.0f);
            *reinterpret_cast<float4*>(hout + (sg * SB + i) * Cout + 4 * og) = r;
        }
    }
}

// ---------------------------------------------------------------------------
// SA grouped MLP + maxpool: block per (batch, center).
// ---------------------------------------------------------------------------
template <int NS, int CF, int C1, int C2, int C3, int NT, int SB>
__global__ void __launch_bounds__(NT)
sa_mlp_kernel(const float* __restrict__ pts, int pstride,
              const float* __restrict__ feats, int fstride,
              const float* __restrict__ centers,
              const int* __restrict__ ball,
              const float* __restrict__ w0, const float* __restrict__ b0,
              const float* __restrict__ w1, const float* __restrict__ b1,
              const float* __restrict__ w2, const float* __restrict__ b2,
              float* __restrict__ out, int M, int N) {
    constexpr int C0 = 3 + CF;
    constexpr int AE = NS * (C0 > C2 ? C0 : C2);
    extern __shared__ float smem[];
    float* bufA = smem;
    float* bufB = smem + AE;
    const int bm = blockIdx.x;
    const int b  = bm / M;
    const int* bi = ball + (size_t)bm * NS;
    const float* ctr = centers + (size_t)bm * 3;

    for (int i = threadIdx.x; i < NS * C0; i += NT) {
        const int s = i / C0, c = i % C0;
        const int p = bi[s];
        float v;
        if (c < 3) v = pts[((size_t)b * N + p) * pstride + c] - ctr[c];
        else       v = feats[((size_t)b * N + p) * fstride + (c - 3)];
        bufA[s * C0 + c] = v;
    }
    __syncthreads();
    mlp_layer<NS, C0, C1, NT, SB>(bufA, bufB, w0, b0); __syncthreads();
    mlp_layer<NS, C1, C2, NT, SB>(bufB, bufA, w1, b1); __syncthreads();
    mlp_layer<NS, C2, C3, NT, SB>(bufA, bufB, w2, b2); __syncthreads();
    float* o = out + (size_t)bm * C3;
    for (int c = threadIdx.x; c < C3; c += NT) {
        float m = bufB[c];
        #pragma unroll 4
        for (int s = 1; s < NS; ++s) m = fmaxf(m, bufB[s * C3 + c]);
        o[c] = m;
    }
}

// ---------------------------------------------------------------------------
// Head MLP + maxpool: block per batch; writes pooled g[768] to global.
// ---------------------------------------------------------------------------
__global__ void __launch_bounds__(128)
head_kernel(const float* __restrict__ nx2, const float* __restrict__ f2,
            const float* __restrict__ w0, const float* __restrict__ b0,
            const float* __restrict__ w1, const float* __restrict__ b1,
            const float* __restrict__ w2, const float* __restrict__ b2,
            float* __restrict__ gout) {
    constexpr int NS = 16, C0 = 259, C1 = 256, C2 = 512, C3 = 768, NT = 128, SB = 8;
    constexpr int AE = NS * C2;
    extern __shared__ float smem[];
    float* bufA = smem;
    float* bufB = smem + AE;
    const int b = blockIdx.x;

    for (int i = threadIdx.x; i < NS * C0; i += NT) {
        const int s = i / C0, c = i % C0;
        float v = (c < 3) ? nx2[((size_t)b * NS + s) * 3 + c]
                          : f2[((size_t)b * NS + s) * 256 + (c - 3)];
        bufA[s * C0 + c] = v;
    }
    __syncthreads();
    mlp_layer<NS, C0, C1, NT, SB>(bufA, bufB, w0, b0); __syncthreads();
    mlp_layer<NS, C1, C2, NT, SB>(bufB, bufA, w1, b1); __syncthreads();
    mlp_layer<NS, C2, C3, NT, SB>(bufA, bufB, w2, b2); __syncthreads();
    float* o = gout + (size_t)b * C3;
    for (int c = threadIdx.x; c < C3; c += NT) {
        float m = bufB[c];
        #pragma unroll 4
        for (int s = 1; s < NS; ++s) m = fmaxf(m, bufB[s * C3 + c]);
        o[c] = m;
    }
}

// ---------------------------------------------------------------------------
// FC: 8 batches per block share fc_w loads. out = g @ fc_w + fc_b.
// ---------------------------------------------------------------------------
__global__ void __launch_bounds__(192)
fc_kernel(const float* __restrict__ g_in, const float* __restrict__ fcw,
          const float* __restrict__ fcb, float* __restrict__ out) {
    constexpr int FCB = 8, C = 768, NT = 192;
    __shared__ float gs[FCB * C];
    const int b0 = blockIdx.x * FCB;
    for (int i = threadIdx.x; i < FCB * C; i += NT)
        gs[i] = g_in[(size_t)b0 * C + i];
    __syncthreads();
    const int og = threadIdx.x;  // 192 == C/4
    const float4 bv = *reinterpret_cast<const float4*>(fcb + 4 * og);
    const ull_t b01 = pk2(bv.x, bv.y), b23 = pk2(bv.z, bv.w);
    ull_t a01[FCB], a23[FCB];
    #pragma unroll
    for (int i = 0; i < FCB; ++i) { a01[i] = b01; a23[i] = b23; }
    const float* wp = fcw + 4 * og;
    #pragma unroll 2
    for (int k = 0; k < C; ++k) {
        const ulonglong2 wq =
            *reinterpret_cast<const ulonglong2*>(wp + (size_t)k * C);
        #pragma unroll
        for (int i = 0; i < FCB; ++i) {
            const ull_t hh = dup2(gs[i * C + k]);
            FMA2(a01[i], hh, wq.x, a01[i]);
            FMA2(a23[i], hh, wq.y, a23[i]);
        }
    }
    #pragma unroll
    for (int i = 0; i < FCB; ++i) {
        const float2 p0 = unpk(a01[i]);
        const float2 p1 = unpk(a23[i]);
        float4 r = make_float4(p0.x, p0.y, p1.x, p1.y);
        *reinterpret_cast<float4*>(out + (size_t)(b0 + i) * C + 4 * og) = r;
    }
}

// ---------------------------------------------------------------------------
// Host launcher
// ---------------------------------------------------------------------------
extern "C" void kernel_launch(void* const* d_in, const int* in_sizes, int n_in,
                              void* d_out, int out_size) {
    const float* x   = (const float*)d_in[0];
    const float* w10 = (const float*)d_in[1];  const float* b10 = (const float*)d_in[2];
    const float* w11 = (const float*)d_in[3];  const float* b11 = (const float*)d_in[4];
    const float* w12 = (const float*)d_in[5];  const float* b12 = (const float*)d_in[6];
    const float* w20 = (const float*)d_in[7];  const float* b20 = (const float*)d_in[8];
    const float* w21 = (const float*)d_in[9];  const float* b21 = (const float*)d_in[10];
    const float* w22 = (const float*)d_in[11]; const float* b22 = (const float*)d_in[12];
    const float* w30 = (const float*)d_in[13]; const float* b30 = (const float*)d_in[14];
    const float* w31 = (const float*)d_in[15]; const float* b31 = (const float*)d_in[16];
    const float* w32 = (const float*)d_in[17]; const float* b32 = (const float*)d_in[18];
    const float* fcw = (const float*)d_in[19]; const float* fcb = (const float*)d_in[20];
    float* out = (float*)d_out;

    int *fps1p, *ball1p, *fps2p, *ball2p;
    float *nx1p, *f1p, *nx2p, *f2p, *gp;
    cudaGetSymbolAddress((void**)&fps1p,  g_fps1);
    cudaGetSymbolAddress((void**)&nx1p,   g_nx1);
    cudaGetSymbolAddress((void**)&ball1p, g_ball1);
    cudaGetSymbolAddress((void**)&f1p,    g_f1);
    cudaGetSymbolAddress((void**)&fps2p,  g_fps2);
    cudaGetSymbolAddress((void**)&nx2p,   g_nx2);
    cudaGetSymbolAddress((void**)&ball2p, g_ball2);
    cudaGetSymbolAddress((void**)&f2p,    g_f2);
    cudaGetSymbolAddress((void**)&gp,     g_g);

    auto sa1 = sa_mlp_kernel<32, 3,   64,  64,  128, 128, 4>;
    auto sa2 = sa_mlp_kernel<32, 128, 128, 128, 256, 128, 8>;

    const int SA1_SMEM   = (32 * 64 + 32 * 128) * 4;   // 24576
    const int SA2_SMEM   = (32 * 131 + 32 * 256) * 4;  // 49536
    const int HEAD_SMEM  = (16 * 512 + 16 * 768) * 4;  // 81920

    cudaFuncSetAttribute(sa2, cudaFuncAttributeMaxDynamicSharedMemorySize, SA2_SMEM);
    cudaFuncSetAttribute(head_kernel, cudaFuncAttributeMaxDynamicSharedMemorySize, HEAD_SMEM);

    // SA1
    fps1_kernel<<<B_TOT, 1024>>>(x, fps1p, nx1p);
    ball_kernel<<<(B_TOT * M1 * 32 + 255) / 256, 256>>>(
        x, 6, nx1p, M1, N1, (float)(0.2 * 0.2), ball1p);
    sa1<<<B_TOT * M1, 128, SA1_SMEM>>>(x, 6, x + 3, 6, nx1p, ball1p,
                                       w10, b10, w11, b11, w12, b12, f1p, M1, N1);
    // SA2
    fps2_kernel<<<(B_TOT * 32 + 127) / 128, 128>>>(nx1p, fps2p, nx2p);
    ball_kernel<<<(B_TOT * M2 * 32 + 255) / 256, 256>>>(
        nx1p, 3, nx2p, M2, M1, (float)(0.4 * 0.4), ball2p);
    sa2<<<B_TOT * M2, 128, SA2_SMEM>>>(nx1p, 3, f1p, 128, nx2p, ball2p,
                                       w20, b20, w21, b21, w22, b22, f2p, M2, M1);
    // Head + FC
    head_kernel<<<B_TOT, 128, HEAD_SMEM>>>(nx2p, f2p, w30, b30, w31, b31,
                                           w32, b32, gp);
    fc_kernel<<<B_TOT / 8, 192>>>(gp, fcw, fcb, out);
}

// round 3
// speedup vs baseline: 2.3972x; 1.0138x over previous
#include <cuda_runtime.h>
#include <math.h>
#include <stdint.h>

// ---------------------------------------------------------------------------
// PointNet++ encoder forward. B=2048 clouds, N=1024 pts, 6 ch.
// SA1: fps 32, ball r=.2 ns=32, MLP 6->64->64->128, max
// SA2: fps 16, ball r=.4 ns=32, MLP 131->128->128->256, max
// Head: 259 -> 256 -> 512 -> 768, max over 16, FC 768->768
// ---------------------------------------------------------------------------

#define B_TOT 2048
#define N1    1024
#define M1    32
#define M2    16
#define NSMP  32

__device__ int   g_fps1 [B_TOT * M1];
__device__ float g_nx1  [B_TOT * M1 * 3];
__device__ int   g_ball1[B_TOT * M1 * NSMP];
__device__ float g_f1   [B_TOT * M1 * 128];
__device__ int   g_fps2 [B_TOT * M2];
__device__ float g_nx2  [B_TOT * M2 * 3];
__device__ int   g_ball2[B_TOT * M2 * NSMP];
__device__ float g_f2   [B_TOT * M2 * 256];
__device__ float g_g    [B_TOT * 768];

// ---- packed f32x2 helpers ---------------------------------------------------
typedef unsigned long long ull_t;

__device__ __forceinline__ ull_t dup2(float v) {
    ull_t r; unsigned u = __float_as_uint(v);
    asm("mov.b64 %0, {%1, %1};" : "=l"(r) : "r"(u));
    return r;
}
__device__ __forceinline__ float2 unpk(ull_t p) {
    unsigned lo, hi;
    asm("mov.b64 {%0, %1}, %2;" : "=r"(lo), "=r"(hi) : "l"(p));
    return make_float2(__uint_as_float(lo), __uint_as_float(hi));
}
#define FMA2(d, a, b, c) \
    asm("fma.rn.f32x2 %0, %1, %2, %3;" : "=l"(d) : "l"(a), "l"(b), "l"(c))

#define BNS_F 0.99999500003749968f   // 1/sqrt(1+1e-5)

// ---------------------------------------------------------------------------
// FPS stage 1: block per batch, 1024 threads, warp-shuffle argmax.
// ---------------------------------------------------------------------------
__global__ void fps1_kernel(const float* __restrict__ x,
                            int* __restrict__ fidx, float* __restrict__ nxyz) {
    __shared__ float swv[32];
    __shared__ int   swi[32];
    __shared__ float cur[3];
    __shared__ int   slast;
    const int b = blockIdx.x;
    const int t = threadIdx.x;
    const int warp = t >> 5, lane = t & 31;
    const float* p = x + ((size_t)b * N1 + t) * 6;
    const float px = p[0], py = p[1], pz = p[2];
    float dist = 1e10f;
    if (t == 0) {
        fidx[b * M1] = 0;
        float* o = nxyz + (size_t)b * M1 * 3;
        o[0] = px; o[1] = py; o[2] = pz;
    }
    int last = 0;
    for (int it = 1; it < M1; ++it) {
        if (t == last) { cur[0] = px; cur[1] = py; cur[2] = pz; }
        __syncthreads();
        float dx = __fsub_rn(px, cur[0]);
        float dy = __fsub_rn(py, cur[1]);
        float dz = __fsub_rn(pz, cur[2]);
        float d  = __fadd_rn(__fadd_rn(__fmul_rn(dx, dx), __fmul_rn(dy, dy)),
                             __fmul_rn(dz, dz));
        dist = fminf(dist, d);
        float v = dist; int vi = t;
        #pragma unroll
        for (int off = 16; off; off >>= 1) {
            float v2 = __shfl_xor_sync(0xffffffffu, v, off);
            int   i2 = __shfl_xor_sync(0xffffffffu, vi, off);
            if (v2 > v || (v2 == v && i2 < vi)) { v = v2; vi = i2; }
        }
        if (lane == 0) { swv[warp] = v; swi[warp] = vi; }
        __syncthreads();
        if (warp == 0) {
            float wv = swv[lane]; int wi = swi[lane];
            #pragma unroll
            for (int off = 16; off; off >>= 1) {
                float v2 = __shfl_xor_sync(0xffffffffu, wv, off);
                int   i2 = __shfl_xor_sync(0xffffffffu, wi, off);
                if (v2 > wv || (v2 == wv && i2 < wi)) { wv = v2; wi = i2; }
            }
            if (lane == 0) { slast = wi; fidx[b * M1 + it] = wi; }
        }
        __syncthreads();
        last = slast;
        if (t == last) {
            float* o = nxyz + ((size_t)b * M1 + it) * 3;
            o[0] = px; o[1] = py; o[2] = pz;
        }
    }
}

// ---------------------------------------------------------------------------
// FPS stage 2: warp per batch.
// ---------------------------------------------------------------------------
__global__ void fps2_kernel(const float* __restrict__ pts,
                            int* __restrict__ fidx, float* __restrict__ nxyz) {
    const int gw   = (blockIdx.x * blockDim.x + threadIdx.x) >> 5;
    const int lane = threadIdx.x & 31;
    if (gw >= B_TOT) return;
    const float* pb = pts + (size_t)gw * M1 * 3;
    const float px = pb[lane * 3 + 0], py = pb[lane * 3 + 1], pz = pb[lane * 3 + 2];
    float dist = 1e10f;
    if (lane == 0) {
        fidx[gw * M2] = 0;
        float* o = nxyz + (size_t)gw * M2 * 3;
        o[0] = px; o[1] = py; o[2] = pz;
    }
    int last = 0;
    for (int it = 1; it < M2; ++it) {
        const float cx = __shfl_sync(0xffffffffu, px, last);
        const float cy = __shfl_sync(0xffffffffu, py, last);
        const float cz = __shfl_sync(0xffffffffu, pz, last);
        float dx = __fsub_rn(px, cx), dy = __fsub_rn(py, cy), dz = __fsub_rn(pz, cz);
        float d  = __fadd_rn(__fadd_rn(__fmul_rn(dx, dx), __fmul_rn(dy, dy)),
                             __fmul_rn(dz, dz));
        dist = fminf(dist, d);
        float v = dist; int vi = lane;
        #pragma unroll
        for (int off = 16; off; off >>= 1) {
            float v2 = __shfl_xor_sync(0xffffffffu, v, off);
            int   i2 = __shfl_xor_sync(0xffffffffu, vi, off);
            if (v2 > v || (v2 == v && i2 < vi)) { v = v2; vi = i2; }
        }
        last = vi;
        if (lane == 0) fidx[gw * M2 + it] = last;
        if (lane == last) {
            float* o = nxyz + ((size_t)gw * M2 + it) * 3;
            o[0] = px; o[1] = py; o[2] = pz;
        }
    }
}

// ---------------------------------------------------------------------------
// Ball query (expanded distance form, identical to reference einsum path).
// ---------------------------------------------------------------------------
__global__ void ball_kernel(const float* __restrict__ pts, int pstride,
                            const float* __restrict__ centers,
                            int M, int N, float r2, int* __restrict__ out) {
    const int gw   = (blockIdx.x * blockDim.x + threadIdx.x) >> 5;
    const int lane = threadIdx.x & 31;
    if (gw >= B_TOT * M) return;
    const int b = gw / M;
    const float* c = centers + (size_t)gw * 3;
    const float cx = c[0], cy = c[1], cz = c[2];
    const float cn = __fadd_rn(__fadd_rn(__fmul_rn(cx, cx), __fmul_rn(cy, cy)),
                               __fmul_rn(cz, cz));
    int* o = out + (size_t)gw * NSMP;
    int cnt = 0, first = -1;
    for (int base = 0; base < N && cnt < NSMP; base += 32) {
        const float* pp = pts + ((size_t)b * N + base + lane) * pstride;
        const float px = pp[0], py = pp[1], pz = pp[2];
        const float pn = __fadd_rn(__fadd_rn(__fmul_rn(px, px), __fmul_rn(py, py)),
                                   __fmul_rn(pz, pz));
        const float dt = __fadd_rn(__fadd_rn(__fmul_rn(cx, px), __fmul_rn(cy, py)),
                                   __fmul_rn(cz, pz));
        const float d2 = __fsub_rn(__fadd_rn(cn, pn), __fmul_rn(2.0f, dt));
        const bool hit = d2 < r2;
        const unsigned mask = __ballot_sync(0xffffffffu, hit);
        if (first < 0 && mask) first = base + __ffs(mask) - 1;
        const int pos = cnt + __popc(mask & ((1u << lane) - 1u));
        if (hit && pos < NSMP) o[pos] = base + lane;
        cnt += __popc(mask);
    }
    if (cnt > NSMP) cnt = NSMP;
    for (int k = cnt + lane; k < NSMP; k += 32) o[k] = first;
}

// ---------------------------------------------------------------------------
// Dense layer on transposed activations.
//   aIn : smem, [Cin][SP] (sample index contiguous), aOut: smem [Cout][SP]
//   w   : [Cin][Cout] row-major (smem or global), bias: global [Cout]
//   Thread owns OC channels (strided by OG) x SB samples. Acts load as
//   broadcast LDS.128; weights as OC scalar loads + dup; FFMA2 accumulate.
// ---------------------------------------------------------------------------
template <int S, int SP, int Cin, int Cout, int OC, int SB, int NT>
__device__ __forceinline__ void layer_dense(const float* __restrict__ aIn,
                                            float* __restrict__ aOut,
                                            const float* __restrict__ w,
                                            const float* __restrict__ bias) {
    constexpr int OG = Cout / OC;
    constexpr int SG = S / SB;
    constexpr int NP = SB / 2;
    constexpr int NL = SB / 4;
    for (int task = threadIdx.x; task < OG * SG; task += NT) {
        const int og = task % OG;
        const int s0 = (task / OG) * SB;
        ull_t acc[OC][NP];
        #pragma unroll
        for (int j = 0; j < OC; ++j)
            #pragma unroll
            for (int p = 0; p < NP; ++p) acc[j][p] = 0ull;
        const float* ain = aIn + s0;
        #pragma unroll 4
        for (int k = 0; k < Cin; ++k) {
            ulonglong2 ap[NL];
            #pragma unroll
            for (int l = 0; l < NL; ++l)
                ap[l] = *reinterpret_cast<const ulonglong2*>(ain + k * SP + 4 * l);
            #pragma unroll
            for (int j = 0; j < OC; ++j) {
                const ull_t wd = dup2(w[k * Cout + og + j * OG]);
                #pragma unroll
                for (int l = 0; l < NL; ++l) {
                    FMA2(acc[j][2*l],   ap[l].x, wd, acc[j][2*l]);
                    FMA2(acc[j][2*l+1], ap[l].y, wd, acc[j][2*l+1]);
                }
            }
        }
        #pragma unroll
        for (int j = 0; j < OC; ++j) {
            const int c = og + j * OG;
            const float bv = bias[c];
            float* op = aOut + c * SP + s0;
            #pragma unroll
            for (int l = 0; l < NL; ++l) {
                const float2 v0 = unpk(acc[j][2*l]);
                const float2 v1 = unpk(acc[j][2*l+1]);
                float4 r;
                r.x = fmaxf((v0.x + bv) * BNS_F, 0.0f);
                r.y = fmaxf((v0.y + bv) * BNS_F, 0.0f);
                r.z = fmaxf((v1.x + bv) * BNS_F, 0.0f);
                r.w = fmaxf((v1.y + bv) * BNS_F, 0.0f);
                *reinterpret_cast<float4*>(op + 4 * l) = r;
            }
        }
    }
}

// ---------------------------------------------------------------------------
// Final layer fused with max-pool over NSC samples per group.
// Thread owns (group, OC channels); running max of raw dots, epilogue once
// (max commutes exactly with monotone +bias,*BNS,relu).
// gout: base for group 0 of this block (column offset pre-applied), ldo = row
// stride of the full output tensor.
// ---------------------------------------------------------------------------
template <int S, int SP, int Cin, int Cout, int OC, int SB, int NSC, int NT>
__device__ __forceinline__ void layer_maxout(const float* __restrict__ aIn,
                                             const float* __restrict__ w,
                                             const float* __restrict__ bias,
                                             float* __restrict__ gout, int ldo) {
    constexpr int OG  = Cout / OC;
    constexpr int NG  = S / NSC;
    constexpr int NP  = SB / 2;
    constexpr int NL  = SB / 4;
    constexpr int NCH = NSC / SB;
    for (int task = threadIdx.x; task < NG * OG; task += NT) {
        const int og = task % OG;
        const int g  = task / OG;
        float m[OC];
        #pragma unroll
        for (int j = 0; j < OC; ++j) m[j] = -3.0e38f;
        #pragma unroll 1
        for (int ch = 0; ch < NCH; ++ch) {
            const int s0 = g * NSC + ch * SB;
            ull_t acc[OC][NP];
            #pragma unroll
            for (int j = 0; j < OC; ++j)
                #pragma unroll
                for (int p = 0; p < NP; ++p) acc[j][p] = 0ull;
            const float* ain = aIn + s0;
            #pragma unroll 4
            for (int k = 0; k < Cin; ++k) {
                ulonglong2 ap[NL];
                #pragma unroll
                for (int l = 0; l < NL; ++l)
                    ap[l] = *reinterpret_cast<const ulonglong2*>(ain + k * SP + 4 * l);
                #pragma unroll
                for (int j = 0; j < OC; ++j) {
                    const ull_t wd = dup2(w[k * Cout + og + j * OG]);
                    #pragma unroll
                    for (int l = 0; l < NL; ++l) {
                        FMA2(acc[j][2*l],   ap[l].x, wd, acc[j][2*l]);
                        FMA2(acc[j][2*l+1], ap[l].y, wd, acc[j][2*l+1]);
                    }
                }
            }
            #pragma unroll
            for (int j = 0; j < OC; ++j)
                #pragma unroll
                for (int p = 0; p < NP; ++p) {
                    const float2 v = unpk(acc[j][p]);
                    m[j] = fmaxf(m[j], fmaxf(v.x, v.y));
                }
        }
        #pragma unroll
        for (int j = 0; j < OC; ++j) {
            const int c = og + j * OG;
            gout[(size_t)g * ldo + c] = fmaxf((m[j] + bias[c]) * BNS_F, 0.0f);
        }
    }
}

template <int NT>
__device__ __forceinline__ void copy_w4(float* dst, const float* __restrict__ src, int n) {
    for (int i = threadIdx.x; i < n / 4; i += NT)
        reinterpret_cast<float4*>(dst)[i] =
            reinterpret_cast<const float4*>(src)[i];
}

// ---------------------------------------------------------------------------
// SA1: 8 centers/block, 256 samples, all weights in smem.
// ---------------------------------------------------------------------------
__global__ void __launch_bounds__(256)
sa1_kernel(const float* __restrict__ x, const float* __restrict__ nx1,
           const int* __restrict__ ball,
           const float* __restrict__ w0, const float* __restrict__ b0,
           const float* __restrict__ w1, const float* __restrict__ b1,
           const float* __restrict__ w2, const float* __restrict__ b2,
           float* __restrict__ out) {
    constexpr int S = 256, SP = 260, NT = 256;
    constexpr int W0N = 6 * 64, W1N = 64 * 64, W2N = 64 * 128;
    extern __shared__ float smem[];
    float* ws0  = smem;                 // 384
    float* ws1  = ws0 + W0N;            // 4096
    float* ws2  = ws1 + W1N;            // 8192
    float* bufA = ws2 + W2N;            // 64*260
    float* bufB = bufA + 64 * SP;       // 64*260

    const int bm0 = blockIdx.x * 8;     // first center (global)
    const int b   = bm0 / M1;

    copy_w4<NT>(ws0, w0, W0N);
    copy_w4<NT>(ws1, w1, W1N);
    copy_w4<NT>(ws2, w2, W2N);
    for (int i = threadIdx.x; i < S * 6; i += NT) {
        const int c = i / S, s = i % S;
        const int center = bm0 + (s >> 5);
        const int p = ball[center * NSMP + (s & 31)];
        float v = x[((size_t)b * N1 + p) * 6 + c];
        if (c < 3) v -= nx1[(size_t)center * 3 + c];
        bufA[c * SP + s] = v;
    }
    __syncthreads();
    layer_dense<S, SP, 6, 64, 4, 8, NT>(bufA, bufB, ws0, b0);
    __syncthreads();
    layer_dense<S, SP, 64, 64, 4, 8, NT>(bufB, bufA, ws1, b1);
    __syncthreads();
    layer_maxout<S, SP, 64, 128, 4, 8, 32, NT>(bufA, ws2, b2,
                                               out + (size_t)bm0 * 128, 128);
}

// ---------------------------------------------------------------------------
// SA2: 4 centers/block, 128 samples, per-layer weight staging (layer3 split).
// ---------------------------------------------------------------------------
__global__ void __launch_bounds__(256)
sa2_kernel(const float* __restrict__ nx1, const float* __restrict__ f1,
           const float* __restrict__ nx2, const int* __restrict__ ball,
           const float* __restrict__ w0, const float* __restrict__ b0,
           const float* __restrict__ w1, const float* __restrict__ b1,
           const float* __restrict__ w2, const float* __restrict__ b2,
           float* __restrict__ out) {
    constexpr int S = 128, SP = 132, NT = 256;
    extern __shared__ float smem[];
    float* wbuf = smem;                   // max 131*128
    float* bufA = wbuf + 131 * 128;       // 131*132
    float* bufB = bufA + 131 * SP;        // 128*132

    const int bm0 = blockIdx.x * 4;       // first center (global)
    const int b   = bm0 / M2;

    copy_w4<NT>(wbuf, w0, 131 * 128);
    for (int i = threadIdx.x; i < S * 131; i += NT) {
        const int c = i / S, s = i % S;
        const int center = bm0 + (s >> 5);
        const int p = ball[center * NSMP + (s & 31)];
        float v;
        if (c < 3) v = nx1[((size_t)b * M1 + p) * 3 + c] - nx2[(size_t)center * 3 + c];
        else       v = f1[((size_t)b * M1 + p) * 128 + (c - 3)];
        bufA[c * SP + s] = v;
    }
    __syncthreads();
    layer_dense<S, SP, 131, 128, 4, 8, NT>(bufA, bufB, wbuf, b0);
    __syncthreads();
    copy_w4<NT>(wbuf, w1, 128 * 128);
    __syncthreads();
    layer_dense<S, SP, 128, 128, 4, 8, NT>(bufB, bufA, wbuf, b1);
    __syncthreads();
    // layer3 Cout=256 in two 128-wide halves
    #pragma unroll 1
    for (int h = 0; h < 2; ++h) {
        for (int i = threadIdx.x; i < 128 * 128 / 4; i += NT) {
            const int row = (i * 4) >> 7, col = (i * 4) & 127;
            reinterpret_cast<float4*>(wbuf)[i] =
                *reinterpret_cast<const float4*>(w2 + row * 256 + h * 128 + col);
        }
        __syncthreads();
        layer_maxout<S, SP, 128, 128, 2, 8, 32, NT>(
            bufA, wbuf, b2 + h * 128, out + (size_t)bm0 * 256 + h * 128, 256);
        __syncthreads();
    }
}

// ---------------------------------------------------------------------------
// Head: 4 batches/block (64 samples), SB=16 (weights read once per block,
// via LDG). Writes pooled g[768] per batch.
// ---------------------------------------------------------------------------
__global__ void __launch_bounds__(256)
head_kernel(const float* __restrict__ nx2, const float* __restrict__ f2,
            const float* __restrict__ w0, const float* __restrict__ b0,
            const float* __restrict__ w1, const float* __restrict__ b1,
            const float* __restrict__ w2, const float* __restrict__ b2,
            float* __restrict__ gout) {
    constexpr int S = 64, SP = 68, NT = 256;
    extern __shared__ float smem[];
    float* bufA = smem;                 // 512*68
    float* bufB = bufA + 512 * SP;      // 256*68

    const int b0b = blockIdx.x * 4;
    for (int i = threadIdx.x; i < S * 259; i += NT) {
        const int c = i / S, s = i % S;
        const int batch = b0b + (s >> 4);
        const int samp  = s & 15;
        float v = (c < 3) ? nx2[((size_t)batch * M2 + samp) * 3 + c]
                          : f2[((size_t)batch * M2 + samp) * 256 + (c - 3)];
        bufA[c * SP + s] = v;
    }
    __syncthreads();
    layer_dense<S, SP, 259, 256, 2, 16, NT>(bufA, bufB, w0, b0);
    __syncthreads();
    layer_dense<S, SP, 256, 512, 2, 16, NT>(bufB, bufA, w1, b1);
    __syncthreads();
    layer_maxout<S, SP, 512, 768, 2, 16, 16, NT>(bufA, w2, b2,
                                                 gout + (size_t)b0b * 768, 768);
}

// ---------------------------------------------------------------------------
// FC: 16 batches/block share fc_w loads. out = g @ fc_w + fc_b.
// ---------------------------------------------------------------------------
__global__ void __launch_bounds__(192)
fc_kernel(const float* __restrict__ g_in, const float* __restrict__ fcw,
          const float* __restrict__ fcb, float* __restrict__ out) {
    constexpr int FCB = 16, C = 768, NT = 192;
    __shared__ float gs[FCB * C];
    const int b0 = blockIdx.x * FCB;
    for (int i = threadIdx.x; i < FCB * C; i += NT)
        gs[i] = g_in[(size_t)b0 * C + i];
    __syncthreads();
    const int og = threadIdx.x;  // 192 == C/4
    const float4 bv = *reinterpret_cast<const float4*>(fcb + 4 * og);
    ull_t a01[FCB], a23[FCB];
    #pragma unroll
    for (int i = 0; i < FCB; ++i) { a01[i] = 0ull; a23[i] = 0ull; }
    const float* wp = fcw + 4 * og;
    #pragma unroll 2
    for (int k = 0; k < C; ++k) {
        const ulonglong2 wq =
            *reinterpret_cast<const ulonglong2*>(wp + (size_t)k * C);
        #pragma unroll
        for (int i = 0; i < FCB; ++i) {
            const ull_t hh = dup2(gs[i * C + k]);
            FMA2(a01[i], hh, wq.x, a01[i]);
            FMA2(a23[i], hh, wq.y, a23[i]);
        }
    }
    #pragma unroll
    for (int i = 0; i < FCB; ++i) {
        const float2 p0 = unpk(a01[i]);
        const float2 p1 = unpk(a23[i]);
        float4 r = make_float4(p0.x + bv.x, p0.y + bv.y, p1.x + bv.z, p1.y + bv.w);
        *reinterpret_cast<float4*>(out + (size_t)(b0 + i) * C + 4 * og) = r;
    }
}

// ---------------------------------------------------------------------------
// Host launcher
// ---------------------------------------------------------------------------
extern "C" void kernel_launch(void* const* d_in, const int* in_sizes, int n_in,
                              void* d_out, int out_size) {
    const float* x   = (const float*)d_in[0];
    const float* w10 = (const float*)d_in[1];  const float* b10 = (const float*)d_in[2];
    const float* w11 = (const float*)d_in[3];  const float* b11 = (const float*)d_in[4];
    const float* w12 = (const float*)d_in[5];  const float* b12 = (const float*)d_in[6];
    const float* w20 = (const float*)d_in[7];  const float* b20 = (const float*)d_in[8];
    const float* w21 = (const float*)d_in[9];  const float* b21 = (const float*)d_in[10];
    const float* w22 = (const float*)d_in[11]; const float* b22 = (const float*)d_in[12];
    const float* w30 = (const float*)d_in[13]; const float* b30 = (const float*)d_in[14];
    const float* w31 = (const float*)d_in[15]; const float* b31 = (const float*)d_in[16];
    const float* w32 = (const float*)d_in[17]; const float* b32 = (const float*)d_in[18];
    const float* fcw = (const float*)d_in[19]; const float* fcb = (const float*)d_in[20];
    float* out = (float*)d_out;

    int *fps1p, *ball1p, *fps2p, *ball2p;
    float *nx1p, *f1p, *nx2p, *f2p, *gp;
    cudaGetSymbolAddress((void**)&fps1p,  g_fps1);
    cudaGetSymbolAddress((void**)&nx1p,   g_nx1);
    cudaGetSymbolAddress((void**)&ball1p, g_ball1);
    cudaGetSymbolAddress((void**)&f1p,    g_f1);
    cudaGetSymbolAddress((void**)&fps2p,  g_fps2);
    cudaGetSymbolAddress((void**)&nx2p,   g_nx2);
    cudaGetSymbolAddress((void**)&ball2p, g_ball2);
    cudaGetSymbolAddress((void**)&f2p,    g_f2);
    cudaGetSymbolAddress((void**)&gp,     g_g);

    const int SA1_SMEM  = (6*64 + 64*64 + 64*128 + 2 * 64 * 260) * 4;   // 183.8KB
    const int SA2_SMEM  = (131*128 + 131*132 + 128*132) * 4;            // 203.8KB
    const int HEAD_SMEM = (512*68 + 256*68) * 4;                        // 208.9KB

    cudaFuncSetAttribute(sa1_kernel,  cudaFuncAttributeMaxDynamicSharedMemorySize, SA1_SMEM);
    cudaFuncSetAttribute(sa2_kernel,  cudaFuncAttributeMaxDynamicSharedMemorySize, SA2_SMEM);
    cudaFuncSetAttribute(head_kernel, cudaFuncAttributeMaxDynamicSharedMemorySize, HEAD_SMEM);

    // SA1
    fps1_kernel<<<B_TOT, 1024>>>(x, fps1p, nx1p);
    ball_kernel<<<(B_TOT * M1 * 32 + 255) / 256, 256>>>(
        x, 6, nx1p, M1, N1, (float)(0.2 * 0.2), ball1p);
    sa1_kernel<<<B_TOT * M1 / 8, 256, SA1_SMEM>>>(x, nx1p, ball1p,
        w10, b10, w11, b11, w12, b12, f1p);
    // SA2
    fps2_kernel<<<(B_TOT * 32 + 127) / 128, 128>>>(nx1p, fps2p, nx2p);
    ball_kernel<<<(B_TOT * M2 * 32 + 255) / 256, 256>>>(
        nx1p, 3, nx2p, M2, M1, (float)(0.4 * 0.4), ball2p);
    sa2_kernel<<<B_TOT * M2 / 4, 256, SA2_SMEM>>>(nx1p, f1p, nx2p, ball2p,
        w20, b20, w21, b21, w22, b22, f2p);
    // Head + FC
    head_kernel<<<B_TOT / 4, 256, HEAD_SMEM>>>(nx2p, f2p, w30, b30, w31, b31,
                                               w32, b32, gp);
    fc_kernel<<<B_TOT / 16, 192>>>(gp, fcw, fcb, out);
}

// round 6
// speedup vs baseline: 3.4053x; 1.4205x over previous
#include <cuda_runtime.h>
#include <cuda_bf16.h>
#include <math.h>
#include <stdint.h>

// ---------------------------------------------------------------------------
// PointNet++ encoder forward. B=2048 clouds, N=1024 pts, 6 ch.
// SA1 (scalar): fps 32, ball r=.2 ns=32, MLP 6->64->64->128, max
// SA2 (HMMA bf16x3): fps 16, ball r=.4 ns=32, MLP 131->128->128->256, max
// Head (scalar): 259 -> 256 -> 512 -> 768, max over 16, FC 768->768
// ---------------------------------------------------------------------------

#define B_TOT 2048
#define N1    1024
#define M1    32
#define M2    16
#define NSMP  32

__device__ int   g_fps1 [B_TOT * M1];
__device__ float g_nx1  [B_TOT * M1 * 3];
__device__ int   g_ball1[B_TOT * M1 * NSMP];
__device__ float g_f1   [B_TOT * M1 * 128];
__device__ int   g_fps2 [B_TOT * M2];
__device__ float g_nx2  [B_TOT * M2 * 3];
__device__ int   g_ball2[B_TOT * M2 * NSMP];
__device__ float g_f2   [B_TOT * M2 * 256];
__device__ float g_g    [B_TOT * 768];

// SA2 weights, transposed to [N][Kpad] bf16, split hi/lo ([0]=hi block, [1]=lo).
__device__ __align__(16) __nv_bfloat16 g_w20b[2 * 128 * 152];
__device__ __align__(16) __nv_bfloat16 g_w21b[2 * 128 * 136];
__device__ __align__(16) __nv_bfloat16 g_w22b[2 * 256 * 136];

// ---- packed f32x2 helpers (scalar kernels) ----------------------------------
typedef unsigned long long ull_t;
__device__ __forceinline__ ull_t dup2(float v) {
    ull_t r; unsigned u = __float_as_uint(v);
    asm("mov.b64 %0, {%1, %1};" : "=l"(r) : "r"(u));
    return r;
}
__device__ __forceinline__ float2 unpk(ull_t p) {
    unsigned lo, hi;
    asm("mov.b64 {%0, %1}, %2;" : "=r"(lo), "=r"(hi) : "l"(p));
    return make_float2(__uint_as_float(lo), __uint_as_float(hi));
}
#define FMA2(d, a, b, c) \
    asm("fma.rn.f32x2 %0, %1, %2, %3;" : "=l"(d) : "l"(a), "l"(b), "l"(c))

#define BNS_F 0.99999500003749968f   // 1/sqrt(1+1e-5)

// ---- mma.sync / ldmatrix helpers --------------------------------------------
__device__ __forceinline__ uint32_t smem_to_u32(const void* p) {
    uint32_t a;
    asm("{ .reg .u64 t; cvta.to.shared.u64 t, %1; cvt.u32.u64 %0, t; }"
        : "=r"(a) : "l"(p));
    return a;
}
#define LDSM4(r, a) \
    asm volatile("ldmatrix.sync.aligned.m8n8.x4.shared.b16 {%0,%1,%2,%3}, [%4];" \
                 : "=r"((r)[0]), "=r"((r)[1]), "=r"((r)[2]), "=r"((r)[3]) : "r"(a))

__device__ __forceinline__ void mma_bf16(float* c, const uint32_t* a,
                                         const uint32_t* b) {
    asm volatile(
        "mma.sync.aligned.m16n8k16.row.col.f32.bf16.bf16.f32 "
        "{%0,%1,%2,%3}, {%4,%5,%6,%7}, {%8,%9}, {%0,%1,%2,%3};"
        : "+f"(c[0]), "+f"(c[1]), "+f"(c[2]), "+f"(c[3])
        : "r"(a[0]), "r"(a[1]), "r"(a[2]), "r"(a[3]), "r"(b[0]), "r"(b[1]));
}

// ---------------------------------------------------------------------------
// FPS stage 1: block per batch, 1024 threads, warp-shuffle argmax.
// ---------------------------------------------------------------------------
__global__ void fps1_kernel(const float* __restrict__ x,
                            int* __restrict__ fidx, float* __restrict__ nxyz) {
    __shared__ float swv[32];
    __shared__ int   swi[32];
    __shared__ float cur[3];
    __shared__ int   slast;
    const int b = blockIdx.x;
    const int t = threadIdx.x;
    const int warp = t >> 5, lane = t & 31;
    const float* p = x + ((size_t)b * N1 + t) * 6;
    const float px = p[0], py = p[1], pz = p[2];
    float dist = 1e10f;
    if (t == 0) {
        fidx[b * M1] = 0;
        float* o = nxyz + (size_t)b * M1 * 3;
        o[0] = px; o[1] = py; o[2] = pz;
    }
    int last = 0;
    for (int it = 1; it < M1; ++it) {
        if (t == last) { cur[0] = px; cur[1] = py; cur[2] = pz; }
        __syncthreads();
        float dx = __fsub_rn(px, cur[0]);
        float dy = __fsub_rn(py, cur[1]);
        float dz = __fsub_rn(pz, cur[2]);
        float d  = __fadd_rn(__fadd_rn(__fmul_rn(dx, dx), __fmul_rn(dy, dy)),
                             __fmul_rn(dz, dz));
        dist = fminf(dist, d);
        float v = dist; int vi = t;
        #pragma unroll
        for (int off = 16; off; off >>= 1) {
            float v2 = __shfl_xor_sync(0xffffffffu, v, off);
            int   i2 = __shfl_xor_sync(0xffffffffu, vi, off);
            if (v2 > v || (v2 == v && i2 < vi)) { v = v2; vi = i2; }
        }
        if (lane == 0) { swv[warp] = v; swi[warp] = vi; }
        __syncthreads();
        if (warp == 0) {
            float wv = swv[lane]; int wi = swi[lane];
            #pragma unroll
            for (int off = 16; off; off >>= 1) {
                float v2 = __shfl_xor_sync(0xffffffffu, wv, off);
                int   i2 = __shfl_xor_sync(0xffffffffu, wi, off);
                if (v2 > wv || (v2 == wv && i2 < wi)) { wv = v2; wi = i2; }
            }
            if (lane == 0) { slast = wi; fidx[b * M1 + it] = wi; }
        }
        __syncthreads();
        last = slast;
        if (t == last) {
            float* o = nxyz + ((size_t)b * M1 + it) * 3;
            o[0] = px; o[1] = py; o[2] = pz;
        }
    }
}

// ---------------------------------------------------------------------------
// FPS stage 2: warp per batch.
// ---------------------------------------------------------------------------
__global__ void fps2_kernel(const float* __restrict__ pts,
                            int* __restrict__ fidx, float* __restrict__ nxyz) {
    const int gw   = (blockIdx.x * blockDim.x + threadIdx.x) >> 5;
    const int lane = threadIdx.x & 31;
    if (gw >= B_TOT) return;
    const float* pb = pts + (size_t)gw * M1 * 3;
    const float px = pb[lane * 3 + 0], py = pb[lane * 3 + 1], pz = pb[lane * 3 + 2];
    float dist = 1e10f;
    if (lane == 0) {
        fidx[gw * M2] = 0;
        float* o = nxyz + (size_t)gw * M2 * 3;
        o[0] = px; o[1] = py; o[2] = pz;
    }
    int last = 0;
    for (int it = 1; it < M2; ++it) {
        const float cx = __shfl_sync(0xffffffffu, px, last);
        const float cy = __shfl_sync(0xffffffffu, py, last);
        const float cz = __shfl_sync(0xffffffffu, pz, last);
        float dx = __fsub_rn(px, cx), dy = __fsub_rn(py, cy), dz = __fsub_rn(pz, cz);
        float d  = __fadd_rn(__fadd_rn(__fmul_rn(dx, dx), __fmul_rn(dy, dy)),
                             __fmul_rn(dz, dz));
        dist = fminf(dist, d);
        float v = dist; int vi = lane;
        #pragma unroll
        for (int off = 16; off; off >>= 1) {
            float v2 = __shfl_xor_sync(0xffffffffu, v, off);
            int   i2 = __shfl_xor_sync(0xffffffffu, vi, off);
            if (v2 > v || (v2 == v && i2 < vi)) { v = v2; vi = i2; }
        }
        last = vi;
        if (lane == 0) fidx[gw * M2 + it] = last;
        if (lane == last) {
            float* o = nxyz + ((size_t)gw * M2 + it) * 3;
            o[0] = px; o[1] = py; o[2] = pz;
        }
    }
}

// ---------------------------------------------------------------------------
// Ball query (expanded distance form, identical to reference einsum path).
// ---------------------------------------------------------------------------
__global__ void ball_kernel(const float* __restrict__ pts, int pstride,
                            const float* __restrict__ centers,
                            int M, int N, float r2, int* __restrict__ out) {
    const int gw   = (blockIdx.x * blockDim.x + threadIdx.x) >> 5;
    const int lane = threadIdx.x & 31;
    if (gw >= B_TOT * M) return;
    const int b = gw / M;
    const float* c = centers + (size_t)gw * 3;
    const float cx = c[0], cy = c[1], cz = c[2];
    const float cn = __fadd_rn(__fadd_rn(__fmul_rn(cx, cx), __fmul_rn(cy, cy)),
                               __fmul_rn(cz, cz));
    int* o = out + (size_t)gw * NSMP;
    int cnt = 0, first = -1;
    for (int base = 0; base < N && cnt < NSMP; base += 32) {
        const float* pp = pts + ((size_t)b * N + base + lane) * pstride;
        const float px = pp[0], py = pp[1], pz = pp[2];
        const float pn = __fadd_rn(__fadd_rn(__fmul_rn(px, px), __fmul_rn(py, py)),
                                   __fmul_rn(pz, pz));
        const float dt = __fadd_rn(__fadd_rn(__fmul_rn(cx, px), __fmul_rn(cy, py)),
                                   __fmul_rn(cz, pz));
        const float d2 = __fsub_rn(__fadd_rn(cn, pn), __fmul_rn(2.0f, dt));
        const bool hit = d2 < r2;
        const unsigned mask = __ballot_sync(0xffffffffu, hit);
        if (first < 0 && mask) first = base + __ffs(mask) - 1;
        const int pos = cnt + __popc(mask & ((1u << lane) - 1u));
        if (hit && pos < NSMP) o[pos] = base + lane;
        cnt += __popc(mask);
    }
    if (cnt > NSMP) cnt = NSMP;
    for (int k = cnt + lane; k < NSMP; k += 32) o[k] = first;
}

// ---------------------------------------------------------------------------
// Scalar MLP machinery (SA1 + head).
// ---------------------------------------------------------------------------
extern __shared__ float dynsmem[];

template <int S, int SP, int Cin, int Cout, int OC, int SB, int NT>
__device__ __forceinline__ void layer_dense(const float* __restrict__ aIn,
                                            float* __restrict__ aOut,
                                            const float* __restrict__ w,
                                            const float* __restrict__ bias) {
    constexpr int OG = Cout / OC;
    constexpr int SG = S / SB;
    constexpr int NP = SB / 2;
    constexpr int NL = SB / 4;
    for (int task = threadIdx.x; task < OG * SG; task += NT) {
        const int og = task % OG;
        const int s0 = (task / OG) * SB;
        ull_t acc[OC][NP];
        #pragma unroll
        for (int j = 0; j < OC; ++j)
            #pragma unroll
            for (int p = 0; p < NP; ++p) acc[j][p] = 0ull;
        const float* ain = aIn + s0;
        #pragma unroll 4
        for (int k = 0; k < Cin; ++k) {
            ulonglong2 ap[NL];
            #pragma unroll
            for (int l = 0; l < NL; ++l)
                ap[l] = *reinterpret_cast<const ulonglong2*>(ain + k * SP + 4 * l);
            #pragma unroll
            for (int j = 0; j < OC; ++j) {
                const ull_t wd = dup2(w[k * Cout + og + j * OG]);
                #pragma unroll
                for (int l = 0; l < NL; ++l) {
                    FMA2(acc[j][2*l],   ap[l].x, wd, acc[j][2*l]);
                    FMA2(acc[j][2*l+1], ap[l].y, wd, acc[j][2*l+1]);
                }
            }
        }
        #pragma unroll
        for (int j = 0; j < OC; ++j) {
            const int c = og + j * OG;
            const float bv = bias[c];
            float* op = aOut + c * SP + s0;
            #pragma unroll
            for (int l = 0; l < NL; ++l) {
                const float2 v0 = unpk(acc[j][2*l]);
                const float2 v1 = unpk(acc[j][2*l+1]);
                float4 r;
                r.x = fmaxf((v0.x + bv) * BNS_F, 0.0f);
                r.y = fmaxf((v0.y + bv) * BNS_F, 0.0f);
                r.z = fmaxf((v1.x + bv) * BNS_F, 0.0f);
                r.w = fmaxf((v1.y + bv) * BNS_F, 0.0f);
                *reinterpret_cast<float4*>(op + 4 * l) = r;
            }
        }
    }
}

template <int S, int SP, int Cin, int Cout, int OC, int SB, int NSC, int NT>
__device__ __forceinline__ void layer_maxout(const float* __restrict__ aIn,
                                             const float* __restrict__ w,
                                             const float* __restrict__ bias,
                                             float* __restrict__ gout, int ldo) {
    constexpr int OG  = Cout / OC;
    constexpr int NG  = S / NSC;
    constexpr int NP  = SB / 2;
    constexpr int NL  = SB / 4;
    constexpr int NCH = NSC / SB;
    for (int task = threadIdx.x; task < NG * OG; task += NT) {
        const int og = task % OG;
        const int g  = task / OG;
        float m[OC];
        #pragma unroll
        for (int j = 0; j < OC; ++j) m[j] = -3.0e38f;
        #pragma unroll 1
        for (int ch = 0; ch < NCH; ++ch) {
            const int s0 = g * NSC + ch * SB;
            ull_t acc[OC][NP];
            #pragma unroll
            for (int j = 0; j < OC; ++j)
                #pragma unroll
                for (int p = 0; p < NP; ++p) acc[j][p] = 0ull;
            const float* ain = aIn + s0;
            #pragma unroll 4
            for (int k = 0; k < Cin; ++k) {
                ulonglong2 ap[NL];
                #pragma unroll
                for (int l = 0; l < NL; ++l)
                    ap[l] = *reinterpret_cast<const ulonglong2*>(ain + k * SP + 4 * l);
                #pragma unroll
                for (int j = 0; j < OC; ++j) {
                    const ull_t wd = dup2(w[k * Cout + og + j * OG]);
                    #pragma unroll
                    for (int l = 0; l < NL; ++l) {
                        FMA2(acc[j][2*l],   ap[l].x, wd, acc[j][2*l]);
                        FMA2(acc[j][2*l+1], ap[l].y, wd, acc[j][2*l+1]);
                    }
                }
            }
            #pragma unroll
            for (int j = 0; j < OC; ++j)
                #pragma unroll
                for (int p = 0; p < NP; ++p) {
                    const float2 v = unpk(acc[j][p]);
                    m[j] = fmaxf(m[j], fmaxf(v.x, v.y));
                }
        }
        #pragma unroll
        for (int j = 0; j < OC; ++j) {
            const int c = og + j * OG;
            gout[(size_t)g * ldo + c] = fmaxf((m[j] + bias[c]) * BNS_F, 0.0f);
        }
    }
}

template <int NT>
__device__ __forceinline__ void copy_w4(float* dst, const float* __restrict__ src, int n) {
    for (int i = threadIdx.x; i < n / 4; i += NT)
        reinterpret_cast<float4*>(dst)[i] =
            reinterpret_cast<const float4*>(src)[i];
}

// ---------------------------------------------------------------------------
// SA1 (scalar): 8 centers/block, 256 samples, all weights in smem.
// ---------------------------------------------------------------------------
__global__ void __launch_bounds__(256)
sa1_kernel(const float* __restrict__ x, const float* __restrict__ nx1,
           const int* __restrict__ ball,
           const float* __restrict__ w0, const float* __restrict__ b0,
           const float* __restrict__ w1, const float* __restrict__ b1,
           const float* __restrict__ w2, const float* __restrict__ b2,
           float* __restrict__ out) {
    constexpr int S = 256, SP = 260, NT = 256;
    constexpr int W0N = 6 * 64, W1N = 64 * 64, W2N = 64 * 128;
    float* smem = dynsmem;
    float* ws0  = smem;
    float* ws1  = ws0 + W0N;
    float* ws2  = ws1 + W1N;
    float* bufA = ws2 + W2N;
    float* bufB = bufA + 64 * SP;

    const int bm0 = blockIdx.x * 8;
    const int b   = bm0 / M1;

    copy_w4<NT>(ws0, w0, W0N);
    copy_w4<NT>(ws1, w1, W1N);
    copy_w4<NT>(ws2, w2, W2N);
    for (int i = threadIdx.x; i < S * 6; i += NT) {
        const int c = i / S, s = i % S;
        const int center = bm0 + (s >> 5);
        const int p = ball[center * NSMP + (s & 31)];
        float v = x[((size_t)b * N1 + p) * 6 + c];
        if (c < 3) v -= nx1[(size_t)center * 3 + c];
        bufA[c * SP + s] = v;
    }
    __syncthreads();
    layer_dense<S, SP, 6, 64, 4, 8, NT>(bufA, bufB, ws0, b0);
    __syncthreads();
    layer_dense<S, SP, 64, 64, 4, 8, NT>(bufB, bufA, ws1, b1);
    __syncthreads();
    layer_maxout<S, SP, 64, 128, 4, 8, 32, NT>(bufA, ws2, b2,
                                               out + (size_t)bm0 * 128, 128);
}

// ---------------------------------------------------------------------------
// SA2 weight prep: transpose to [N][Kpad], split to bf16 hi/lo.
// ---------------------------------------------------------------------------
__global__ void prep_t_kernel(const float* __restrict__ w,
                              __nv_bfloat16* __restrict__ out,
                              int Cin, int Cout, int Kpad) {
    const int total = Cout * Kpad;
    for (int idx = blockIdx.x * blockDim.x + threadIdx.x; idx < total;
         idx += gridDim.x * blockDim.x) {
        const int n = idx / Kpad, kp = idx % Kpad;
        const float v = (kp < Cin) ? w[(size_t)kp * Cout + n] : 0.0f;
        const __nv_bfloat16 hi = __float2bfloat16(v);
        const __nv_bfloat16 lo = __float2bfloat16(v - __bfloat162float(hi));
        out[idx] = hi;
        out[total + idx] = lo;
    }
}

// ---------------------------------------------------------------------------
// SA2 HMMA kernel. 4 centers/block (M=128), bf16x3 via mma.sync m16n8k16.
// smem layout (bytes):
//   A  : hi @0, lo @38912   (L0 stride 304B (Kpad=152), L1/L2 stride 272B)
//   B  : hi @77824, lo @77824+69632   ([N][Kpad] bf16)
//   part @217088 (8 x 128 fp32), biases @221184 (512 fp32)
// ---------------------------------------------------------------------------
#define A_OFF     0u
#define HALF_A    38912u
#define B_OFF     77824u
#define HALF_B    69632u
#define PART_OFF  217088u
#define BIAS_OFF  221184u
#define SA2M_SMEM 223232

// Copy hi and lo weight halves (halfBytes each) into their smem regions.
__device__ __forceinline__ void stage_b(char* smem, const __nv_bfloat16* src,
                                        int halfBytes) {
    float4* dh = (float4*)(smem + B_OFF);
    float4* dl = (float4*)(smem + B_OFF + HALF_B);
    const float4* sh = (const float4*)src;
    const float4* sl = (const float4*)((const char*)src + halfBytes);
    const int n16 = halfBytes / 16;
    for (int i = threadIdx.x; i < n16; i += 256) { dh[i] = sh[i]; dl[i] = sl[i]; }
}

template <int KS>
__device__ __forceinline__ void gemm_pass(uint32_t su, uint32_t aStride,
                                          uint32_t bStride, int nBase, int mw,
                                          int lane, float (&c)[16][4]) {
    const uint32_t aAddr = su + A_OFF + (uint32_t)(mw + (lane & 15)) * aStride +
                           (uint32_t)((lane >> 4) << 4);
    const uint32_t nrow  = (lane & 7) + ((lane >> 4) << 3);
    const uint32_t kcolB = ((lane >> 3) & 1) << 4;
    const uint32_t bAddr = su + B_OFF + (uint32_t)(nBase + nrow) * bStride + kcolB;
    #pragma unroll 1
    for (int ks = 0; ks < KS; ++ks) {
        uint32_t ah[4], al[4];
        LDSM4(ah, aAddr + ks * 32);
        LDSM4(al, aAddr + HALF_A + ks * 32);
        #pragma unroll
        for (int p = 0; p < 8; ++p) {
            uint32_t bh[4], bl[4];
            const uint32_t ba = bAddr + (uint32_t)p * 16u * bStride + ks * 32;
            LDSM4(bh, ba);
            LDSM4(bl, ba + HALF_B);
            mma_bf16(c[2*p],     ah, bh);
            mma_bf16(c[2*p],     ah, bl);
            mma_bf16(c[2*p],     al, bh);
            mma_bf16(c[2*p+1],   ah, bh + 2);
            mma_bf16(c[2*p+1],   ah, bl + 2);
            mma_bf16(c[2*p+1],   al, bh + 2);
        }
    }
}

__device__ __forceinline__ void epi_dense(char* smem, const float* bs, int boff,
                                          float (&c)[16][4], int mw, int lane) {
    const int r0  = mw + (lane >> 2);
    const int ccb = 2 * (lane & 3);
    #pragma unroll
    for (int f = 0; f < 16; ++f) {
        const int cc = (f >> 1) * 16 + (f & 1) * 8 + ccb;
        const float bv0 = bs[boff + cc], bv1 = bs[boff + cc + 1];
        const float v00 = fmaxf((c[f][0] + bv0) * BNS_F, 0.0f);
        const float v01 = fmaxf((c[f][1] + bv1) * BNS_F, 0.0f);
        const float v10 = fmaxf((c[f][2] + bv0) * BNS_F, 0.0f);
        const float v11 = fmaxf((c[f][3] + bv1) * BNS_F, 0.0f);
        __nv_bfloat162 h0 = __floats2bfloat162_rn(v00, v01);
        __nv_bfloat162 l0 = __floats2bfloat162_rn(v00 - __bfloat162float(h0.x),
                                                  v01 - __bfloat162float(h0.y));
        __nv_bfloat162 h1 = __floats2bfloat162_rn(v10, v11);
        __nv_bfloat162 l1 = __floats2bfloat162_rn(v10 - __bfloat162float(h1.x),
                                                  v11 - __bfloat162float(h1.y));
        const uint32_t o0 = (uint32_t)r0 * 272u + (uint32_t)cc * 2u;
        const uint32_t o1 = o0 + 8u * 272u;
        *(uint32_t*)(smem + o0) = *(const uint32_t*)&h0;
        *(uint32_t*)(smem + HALF_A + o0) = *(const uint32_t*)&l0;
        *(uint32_t*)(smem + o1) = *(const uint32_t*)&h1;
        *(uint32_t*)(smem + HALF_A + o1) = *(const uint32_t*)&l1;
    }
}

__global__ void __launch_bounds__(256)
sa2m_kernel(const float* __restrict__ nx1, const float* __restrict__ f1,
            const float* __restrict__ nx2, const int* __restrict__ ball,
            const float* __restrict__ b0_, const float* __restrict__ b1_,
            const float* __restrict__ b2_, float* __restrict__ out) {
    char* smem = (char*)dynsmem;
    const uint32_t su = smem_to_u32(smem);
    const int tid = threadIdx.x;
    const int wid = tid >> 5, lane = tid & 31;
    const int mw  = wid * 16;
    float* bs = (float*)(smem + BIAS_OFF);
    float* part = (float*)(smem + PART_OFF);

    const int bm0 = blockIdx.x * 4;
    const int b   = bm0 / M2;

    if (tid < 128) { bs[tid] = b0_[tid]; bs[128 + tid] = b1_[tid]; }
    bs[256 + tid] = b2_[tid];

    // Gather A(L0): 128 rows x 144 cols (k>=131 zero), bf16 hi/lo, stride 304B.
    {
        const int row = tid >> 1, seg = tid & 1;
        const int center = bm0 + (row >> 5);
        const int p = ball[center * NSMP + (row & 31)];
        const float* nx1r = nx1 + ((size_t)b * M1 + p) * 3;
        const float* ctr  = nx2 + (size_t)center * 3;
        const float* f1r  = f1 + ((size_t)b * M1 + p) * 128;
        #pragma unroll 1
        for (int i = 0; i < 36; ++i) {
            const int k = seg * 72 + 2 * i;
            float v0, v1;
            if (k < 3)        v0 = nx1r[k] - ctr[k];
            else if (k < 131) v0 = f1r[k - 3];
            else              v0 = 0.0f;
            const int k1 = k + 1;
            if (k1 < 3)        v1 = nx1r[k1] - ctr[k1];
            else if (k1 < 131) v1 = f1r[k1 - 3];
            else               v1 = 0.0f;
            __nv_bfloat162 hh = __floats2bfloat162_rn(v0, v1);
            __nv_bfloat162 ll = __floats2bfloat162_rn(v0 - __bfloat162float(hh.x),
                                                      v1 - __bfloat162float(hh.y));
            const uint32_t off = (uint32_t)row * 304u + (uint32_t)k * 2u;
            *(uint32_t*)(smem + off) = *(const uint32_t*)&hh;
            *(uint32_t*)(smem + HALF_A + off) = *(const uint32_t*)&ll;
        }
    }
    stage_b(smem, g_w20b, 128 * 152 * 2);
    __syncthreads();

    float c[16][4];
    // Layer 0: K=144 (9 steps), N=128
    #pragma unroll
    for (int f = 0; f < 16; ++f)
        #pragma unroll
        for (int j = 0; j < 4; ++j) c[f][j] = 0.0f;
    gemm_pass<9>(su, 304u, 304u, 0, mw, lane, c);
    __syncthreads();
    epi_dense(smem, bs, 0, c, mw, lane);
    stage_b(smem, g_w21b, 128 * 136 * 2);
    __syncthreads();

    // Layer 1: K=128 (8 steps), N=128
    #pragma unroll
    for (int f = 0; f < 16; ++f)
        #pragma unroll
        for (int j = 0; j < 4; ++j) c[f][j] = 0.0f;
    gemm_pass<8>(su, 272u, 272u, 0, mw, lane, c);
    __syncthreads();
    epi_dense(smem, bs, 128, c, mw, lane);
    stage_b(smem, g_w22b, 256 * 136 * 2);
    __syncthreads();

    // Layer 2: K=128, N=256 in two halves; fused max over 32 rows per center.
    #pragma unroll 1
    for (int h = 0; h < 2; ++h) {
        #pragma unroll
        for (int f = 0; f < 16; ++f)
            #pragma unroll
            for (int j = 0; j < 4; ++j) c[f][j] = 0.0f;
        gemm_pass<8>(su, 272u, 272u, h * 128, mw, lane, c);
        #pragma unroll
        for (int f = 0; f < 16; ++f) {
            float m0 = fmaxf(c[f][0], c[f][2]);
            float m1 = fmaxf(c[f][1], c[f][3]);
            #pragma unroll
            for (int off = 4; off <= 16; off <<= 1) {
                m0 = fmaxf(m0, __shfl_xor_sync(0xffffffffu, m0, off));
                m1 = fmaxf(m1, __shfl_xor_sync(0xffffffffu, m1, off));
            }
            if (lane < 4) {
                const int cc = (f >> 1) * 16 + (f & 1) * 8 + 2 * lane;
                part[wid * 128 + cc] = m0;
                part[wid * 128 + cc + 1] = m1;
            }
        }
        __syncthreads();
        for (int i = tid; i < 512; i += 256) {
            const int ci = i >> 7, n = i & 127;
            const float v = fmaxf(part[(2 * ci) * 128 + n],
                                  part[(2 * ci + 1) * 128 + n]);
            out[(size_t)(bm0 + ci) * 256 + h * 128 + n] =
                fmaxf((v + bs[256 + h * 128 + n]) * BNS_F, 0.0f);
        }
        __syncthreads();
    }
}

// ---------------------------------------------------------------------------
// Head (scalar): 4 batches/block (64 samples), SB=16.
// ---------------------------------------------------------------------------
__global__ void __launch_bounds__(256)
head_kernel(const float* __restrict__ nx2, const float* __restrict__ f2,
            const float* __restrict__ w0, const float* __restrict__ b0,
            const float* __restrict__ w1, const float* __restrict__ b1,
            const float* __restrict__ w2, const float* __restrict__ b2,
            float* __restrict__ gout) {
    constexpr int S = 64, SP = 68, NT = 256;
    float* bufA = dynsmem;
    float* bufB = bufA + 512 * SP;

    const int b0b = blockIdx.x * 4;
    for (int i = threadIdx.x; i < S * 259; i += NT) {
        const int c = i / S, s = i % S;
        const int batch = b0b + (s >> 4);
        const int samp  = s & 15;
        float v = (c < 3) ? nx2[((size_t)batch * M2 + samp) * 3 + c]
                          : f2[((size_t)batch * M2 + samp) * 256 + (c - 3)];
        bufA[c * SP + s] = v;
    }
    __syncthreads();
    layer_dense<S, SP, 259, 256, 2, 16, NT>(bufA, bufB, w0, b0);
    __syncthreads();
    layer_dense<S, SP, 256, 512, 2, 16, NT>(bufB, bufA, w1, b1);
    __syncthreads();
    layer_maxout<S, SP, 512, 768, 2, 16, 16, NT>(bufA, w2, b2,
                                                 gout + (size_t)b0b * 768, 768);
}

// ---------------------------------------------------------------------------
// FC: 16 batches/block share fc_w loads.
// ---------------------------------------------------------------------------
__global__ void __launch_bounds__(192)
fc_kernel(const float* __restrict__ g_in, const float* __restrict__ fcw,
          const float* __restrict__ fcb, float* __restrict__ out) {
    constexpr int FCB = 16, C = 768, NT = 192;
    __shared__ float gs[FCB * C];
    const int b0 = blockIdx.x * FCB;
    for (int i = threadIdx.x; i < FCB * C; i += NT)
        gs[i] = g_in[(size_t)b0 * C + i];
    __syncthreads();
    const int og = threadIdx.x;
    const float4 bv = *reinterpret_cast<const float4*>(fcb + 4 * og);
    ull_t a01[FCB], a23[FCB];
    #pragma unroll
    for (int i = 0; i < FCB; ++i) { a01[i] = 0ull; a23[i] = 0ull; }
    const float* wp = fcw + 4 * og;
    #pragma unroll 2
    for (int k = 0; k < C; ++k) {
        const ulonglong2 wq =
            *reinterpret_cast<const ulonglong2*>(wp + (size_t)k * C);
        #pragma unroll
        for (int i = 0; i < FCB; ++i) {
            const ull_t hh = dup2(gs[i * C + k]);
            FMA2(a01[i], hh, wq.x, a01[i]);
            FMA2(a23[i], hh, wq.y, a23[i]);
        }
    }
    #pragma unroll
    for (int i = 0; i < FCB; ++i) {
        const float2 p0 = unpk(a01[i]);
        const float2 p1 = unpk(a23[i]);
        float4 r = make_float4(p0.x + bv.x, p0.y + bv.y, p1.x + bv.z, p1.y + bv.w);
        *reinterpret_cast<float4*>(out + (size_t)(b0 + i) * C + 4 * og) = r;
    }
}

// ---------------------------------------------------------------------------
// Host launcher
// ---------------------------------------------------------------------------
extern "C" void kernel_launch(void* const* d_in, const int* in_sizes, int n_in,
                              void* d_out, int out_size) {
    const float* x   = (const float*)d_in[0];
    const float* w10 = (const float*)d_in[1];  const float* b10 = (const float*)d_in[2];
    const float* w11 = (const float*)d_in[3];  const float* b11 = (const float*)d_in[4];
    const float* w12 = (const float*)d_in[5];  const float* b12 = (const float*)d_in[6];
    const float* w20 = (const float*)d_in[7];  const float* b20 = (const float*)d_in[8];
    const float* w21 = (const float*)d_in[9];  const float* b21 = (const float*)d_in[10];
    const float* w22 = (const float*)d_in[11]; const float* b22 = (const float*)d_in[12];
    const float* w30 = (const float*)d_in[13]; const float* b30 = (const float*)d_in[14];
    const float* w31 = (const float*)d_in[15]; const float* b31 = (const float*)d_in[16];
    const float* w32 = (const float*)d_in[17]; const float* b32 = (const float*)d_in[18];
    const float* fcw = (const float*)d_in[19]; const float* fcb = (const float*)d_in[20];
    float* out = (float*)d_out;

    int *fps1p, *ball1p, *fps2p, *ball2p;
    float *nx1p, *f1p, *nx2p, *f2p, *gp;
    __nv_bfloat16 *w20bp, *w21bp, *w22bp;
    cudaGetSymbolAddress((void**)&fps1p,  g_fps1);
    cudaGetSymbolAddress((void**)&nx1p,   g_nx1);
    cudaGetSymbolAddress((void**)&ball1p, g_ball1);
    cudaGetSymbolAddress((void**)&f1p,    g_f1);
    cudaGetSymbolAddress((void**)&fps2p,  g_fps2);
    cudaGetSymbolAddress((void**)&nx2p,   g_nx2);
    cudaGetSymbolAddress((void**)&ball2p, g_ball2);
    cudaGetSymbolAddress((void**)&f2p,    g_f2);
    cudaGetSymbolAddress((void**)&gp,     g_g);
    cudaGetSymbolAddress((void**)&w20bp,  g_w20b);
    cudaGetSymbolAddress((void**)&w21bp,  g_w21b);
    cudaGetSymbolAddress((void**)&w22bp,  g_w22b);

    const int SA1_SMEM  = (6*64 + 64*64 + 64*128 + 2 * 64 * 260) * 4;
    const int HEAD_SMEM = (512*68 + 256*68) * 4;

    cudaFuncSetAttribute(sa1_kernel,  cudaFuncAttributeMaxDynamicSharedMemorySize, SA1_SMEM);
    cudaFuncSetAttribute(sa2m_kernel, cudaFuncAttributeMaxDynamicSharedMemorySize, SA2M_SMEM);
    cudaFuncSetAttribute(head_kernel, cudaFuncAttributeMaxDynamicSharedMemorySize, HEAD_SMEM);

    // Weight prep (deterministic; part of the graph)
    prep_t_kernel<<<76, 256>>>(w20, w20bp, 131, 128, 152);
    prep_t_kernel<<<68, 256>>>(w21, w21bp, 128, 128, 136);
    prep_t_kernel<<<136, 256>>>(w22, w22bp, 128, 256, 136);

    // SA1
    fps1_kernel<<<B_TOT, 1024>>>(x, fps1p, nx1p);
    ball_kernel<<<(B_TOT * M1 * 32 + 255) / 256, 256>>>(
        x, 6, nx1p, M1, N1, (float)(0.2 * 0.2), ball1p);
    sa1_kernel<<<B_TOT * M1 / 8, 256, SA1_SMEM>>>(x, nx1p, ball1p,
        w10, b10, w11, b11, w12, b12, f1p);
    // SA2
    fps2_kernel<<<(B_TOT * 32 + 127) / 128, 128>>>(nx1p, fps2p, nx2p);
    ball_kernel<<<(B_TOT * M2 * 32 + 255) / 256, 256>>>(
        nx1p, 3, nx2p, M2, M1, (float)(0.4 * 0.4), ball2p);
    sa2m_kernel<<<B_TOT * M2 / 4, 256, SA2M_SMEM>>>(nx1p, f1p, nx2p, ball2p,
        b20, b21, b22, f2p);
    // Head + FC
    head_kernel<<<B_TOT / 4, 256, HEAD_SMEM>>>(nx2p, f2p, w30, b30, w31, b31,
                                               w32, b32, gp);
    fc_kernel<<<B_TOT / 16, 192>>>(gp, fcw, fcb, out);
}